// round 16
// baseline (speedup 1.0000x reference)
#include <cuda_runtime.h>

#define NB   8
#define LIN  32768
#define NC1  51
#define NK1  79
#define NSC  9
#define LP1  8192
#define LP2  2048
#define SMAX 64
#define NSLOT 32

// scratch (allocation-free rule: device globals)
__device__ float  g_bufA[30081024];   // ping buffer
__device__ float  g_bufB[7520256];    // pong buffer (= 8*51*9*2048)
__device__ float  g_wT[1800000];      // transposed gg weights [layer][tap][ci][co]
__device__ float  g_psum[408 * SMAX];
__device__ float  g_psqs[408 * SMAX];
__device__ double g_dsum[408 * NSLOT];   // zero-init; re-zeroed by finalize
__device__ double g_dsqs[408 * NSLOT];
__device__ float  g_scale[408];
__device__ float  g_shift[408];
__device__ unsigned int g_tick[16];   // per-BN-stage arrival tickets (self-resetting)

// layer dims for the 9 gg layers: {Cin, Cout, Nk*3}
#define GG_NLAYERS 9
__device__ __constant__ int c_CIN[GG_NLAYERS]  = {51, 51, 51, 102, 102, 204, 204, 204, 408};
__device__ __constant__ int c_COUT[GG_NLAYERS] = {51, 51, 102, 102, 204, 204, 204, 408, 408};
__device__ __constant__ int c_NKK[GG_NLAYERS]  = {9, 3, 9, 3, 9, 3, 3, 9, 3};

// ---------------------------------------------------------------------------
// packed fp32x2 helpers (FFMA2 — only reachable via PTX)
// ---------------------------------------------------------------------------
__device__ __forceinline__ unsigned long long pack2(float lo, float hi) {
    unsigned long long r;
    asm("mov.b64 %0, {%1, %2};" : "=l"(r) : "f"(lo), "f"(hi));
    return r;
}
__device__ __forceinline__ void fma2(unsigned long long& d,
                                     unsigned long long a, unsigned long long b) {
    asm("fma.rn.f32x2 %0, %1, %2, %0;" : "+l"(d) : "l"(a), "l"(b));
}
__device__ __forceinline__ float2 unpack2(unsigned long long v) {
    float2 f;
    asm("mov.b64 {%0, %1}, %2;" : "=f"(f.x), "=f"(f.y) : "l"(v));
    return f;
}

// ---------------------------------------------------------------------------
// finalize tail (last-block-done over double slots): reduces slot partials
// into scale/shift, zeroes slots, resets the ticket. Call from ALL threads.
// ---------------------------------------------------------------------------
__device__ __forceinline__ void bn_finalize_tail(
    const float* __restrict__ gamma, const float* __restrict__ beta,
    int C, double invN, int stage, int tid, int nthreads, unsigned int total)
{
    __shared__ bool last;
    __syncthreads();                      // this block's atomics done
    if (tid == 0) {
        __threadfence();
        last = (atomicAdd(&g_tick[stage], 1u) == total - 1u);
    }
    __syncthreads();
    if (!last) return;
    __threadfence();                      // acquire all partials
    for (int cc = tid; cc < C; cc += nthreads) {
        double sd = 0.0, qd = 0.0;
        #pragma unroll 4
        for (int i = 0; i < NSLOT; ++i) {
            sd += g_dsum[cc * NSLOT + i];
            qd += g_dsqs[cc * NSLOT + i];
            g_dsum[cc * NSLOT + i] = 0.0;
            g_dsqs[cc * NSLOT + i] = 0.0;
        }
        double m   = sd * invN;
        double var = qd * invN - m * m;
        float inv = rsqrtf((float)var + 2e-5f);
        float sc  = gamma[cc] * inv;
        g_scale[cc] = sc;
        g_shift[cc] = beta[cc] - (float)m * sc;
    }
    __syncthreads();
    if (tid == 0) {
        __threadfence();
        g_tick[stage] = 0;                // reset for next graph replay
    }
}

// ---------------------------------------------------------------------------
// One-shot weight transpose for ALL gg layers:
// w[Cout][Cin][NkK] -> wt[tap][ci][co] per layer, concatenated.
// ---------------------------------------------------------------------------
__global__ void wtrans_all_kernel(const float* __restrict__ w0, const float* __restrict__ w1,
                                  const float* __restrict__ w2, const float* __restrict__ w3,
                                  const float* __restrict__ w4, const float* __restrict__ w5,
                                  const float* __restrict__ w6, const float* __restrict__ w7,
                                  const float* __restrict__ w8, float* __restrict__ wt)
{
    const float* ws[GG_NLAYERS] = {w0, w1, w2, w3, w4, w5, w6, w7, w8};
    int total = 0;
    int off[GG_NLAYERS];
    #pragma unroll
    for (int l = 0; l < GG_NLAYERS; ++l) {
        off[l] = total;
        total += c_CIN[l] * c_COUT[l] * c_NKK[l];
    }
    for (int idx = blockIdx.x * blockDim.x + threadIdx.x; idx < total;
         idx += gridDim.x * blockDim.x) {
        int layer = 0;
        #pragma unroll
        for (int l = 1; l < GG_NLAYERS; ++l)
            if (idx >= off[l]) layer = l;
        int local = idx - off[layer];
        int Cout = c_COUT[layer], Cin = c_CIN[layer], NkK = c_NKK[layer];
        int co  = local % Cout;
        int t   = local / Cout;
        int ci  = t % Cin;
        int tap = t / Cin;
        wt[idx] = ws[layer][(co * Cin + ci) * NkK + tap];
    }
}

// ---------------------------------------------------------------------------
// Lift (K=79, dilation 2^s, /2^s) fused with pool4, BN1 STATS, and the
// second pool4 (monotonicity: gamma>0 so relu(bn(max4(A))) needs only max4(A)).
// Writes the TWICE-pooled A2 [8,51,9,2048]; never materializes full A.
// ---------------------------------------------------------------------------
__launch_bounds__(416)
__global__ void lift_pool_kernel(const float* __restrict__ x,
                                 const float* __restrict__ w,
                                 float* __restrict__ out,   // A2 [8][51][9][2048]
                                 const float* __restrict__ gamma,
                                 const float* __restrict__ beta)
{
    extern __shared__ float sm[];
    float* sw = sm;             // [79][52] pre-scaled weights
    float* sx = sm + 79 * 52;   // input window
    const int s = blockIdx.z;
    const int d = 1 << s;
    const float invd = 1.0f / (float)d;
    const int b   = blockIdx.y;
    const int l0  = blockIdx.x * 128;
    const int tid = threadIdx.x;

    for (int t = tid; t < 79 * 52; t += 416) {
        int k = t / 52, co = t - k * 52;
        sw[t] = (co < NC1) ? w[co * NK1 + k] * invd : 0.0f;
    }
    const int nx = 128 + 78 * d + 8;
    const int gb = l0 - 39 * d;
    const float* xb = x + (size_t)b * LIN;
    for (int t = tid; t < nx; t += 416) {
        int g = gb + t;
        sx[t] = (g >= 0 && g < LIN) ? xb[g] : 0.0f;
    }
    __syncthreads();

    const int lg   = tid & 31;
    const int cg   = tid >> 5;
    const int co0  = cg * 4;
    const int base = lg * 4;
    unsigned long long acc2[4][2] = {};

    if (d >= 4) {
        #pragma unroll 4
        for (int k = 0; k < NK1; ++k) {
            ulonglong2 xq = *reinterpret_cast<const ulonglong2*>(&sx[base + k * d]);
            float4 wv = *reinterpret_cast<const float4*>(&sw[k * 52 + co0]);
            float wa[4] = {wv.x, wv.y, wv.z, wv.w};
            #pragma unroll
            for (int r = 0; r < 4; ++r) {
                unsigned long long wp = pack2(wa[r], wa[r]);
                fma2(acc2[r][0], wp, xq.x);
                fma2(acc2[r][1], wp, xq.y);
            }
        }
    } else if (d == 2) {
        float x0 = sx[base], x1 = sx[base+1], x2 = sx[base+2], x3 = sx[base+3];
        for (int k = 0; k < NK1; ++k) {
            float4 wv = *reinterpret_cast<const float4*>(&sw[k * 52 + co0]);
            float wa[4] = {wv.x, wv.y, wv.z, wv.w};
            unsigned long long xp0 = pack2(x0, x1), xp1 = pack2(x2, x3);
            #pragma unroll
            for (int r = 0; r < 4; ++r) {
                unsigned long long wp = pack2(wa[r], wa[r]);
                fma2(acc2[r][0], wp, xp0);
                fma2(acc2[r][1], wp, xp1);
            }
            x0 = x2; x1 = x3;
            x2 = sx[base + 2*k + 4];
            x3 = sx[base + 2*k + 5];
        }
    } else {
        float x0 = sx[base], x1 = sx[base+1], x2 = sx[base+2], x3 = sx[base+3];
        for (int k = 0; k < NK1; ++k) {
            float4 wv = *reinterpret_cast<const float4*>(&sw[k * 52 + co0]);
            float wa[4] = {wv.x, wv.y, wv.z, wv.w};
            unsigned long long xp0 = pack2(x0, x1), xp1 = pack2(x2, x3);
            #pragma unroll
            for (int r = 0; r < 4; ++r) {
                unsigned long long wp = pack2(wa[r], wa[r]);
                fma2(acc2[r][0], wp, xp0);
                fma2(acc2[r][1], wp, xp1);
            }
            x0 = x1; x1 = x2; x2 = x3;
            x3 = sx[base + k + 4];
        }
    }

    // epilogue: A value per (co, pooled pos) -> stats + second pool4 across lanes
    const int lp2  = blockIdx.x * 8 + (lg >> 2);
    const int slot = (blockIdx.x + blockIdx.y * 3 + blockIdx.z * 5) & (NSLOT - 1);
    #pragma unroll
    for (int r = 0; r < 4; ++r) {
        float2 a = unpack2(acc2[r][0]);
        float2 c = unpack2(acc2[r][1]);
        float m = fmaxf(fmaxf(a.x, a.y), fmaxf(c.x, c.y));   // A[b,co,s,lp]

        // BN1 stats over A (full 32-lane reduce)
        float sv = m, qv = m * m;
        #pragma unroll
        for (int del = 16; del > 0; del >>= 1) {
            sv += __shfl_down_sync(0xffffffffu, sv, del);
            qv += __shfl_down_sync(0xffffffffu, qv, del);
        }
        // second pool4 across lane quads
        float p = m;
        p = fmaxf(p, __shfl_xor_sync(0xffffffffu, p, 1));
        p = fmaxf(p, __shfl_xor_sync(0xffffffffu, p, 2));

        int co = co0 + r;
        if (co < NC1) {
            if ((lg & 3) == 0)
                out[(((size_t)b * NC1 + co) * NSC + s) * LP2 + lp2] = p;
            if (lg == 0) {
                atomicAdd(&g_dsum[co * NSLOT + slot], (double)sv);
                atomicAdd(&g_dsqs[co * NSLOT + slot], (double)qv);
            }
        }
    }

    bn_finalize_tail(gamma, beta, NC1, 1.0 / ((double)NB * NSC * LP1), 0,
                     tid, 416, gridDim.x * gridDim.y * gridDim.z);
}

// ---------------------------------------------------------------------------
// GConvGG: tiled GEMM over ci per (i,k) tap, coalesced transposed weights,
// ping-pong double-buffered fills (hoisted fill indexing), partial-last-chunk
// compute. 4x4 thread tile on fp32x2. fuse != 0: BN+ReLU at input-tile load.
// ---------------------------------------------------------------------------
template <int COT, int LT>
__launch_bounds__((COT/4)*(LT/4))
__global__ void gg_kernel(const float* __restrict__ in, const float* __restrict__ wt,
                          float* __restrict__ out,
                          int Cin, int Cout, int Hin, int Nk, int L, int fuse)
{
    const int CIC = 16;
    const int TLn = LT / 4;
    const int NT  = (COT/4) * TLn;
    const int AE  = (CIC * COT) / NT;
    const int BE  = (CIC * LT) / NT;
    __shared__ __align__(16) float As[2][CIC][COT];
    __shared__ __align__(16) float Bs[2][CIC][LT];
    __shared__ float ssc[408], ssh[408];

    const int Hout = Hin - Nk + 1;
    const int s   = blockIdx.z % Hout;
    const int b   = blockIdx.z / Hout;
    const int co0 = blockIdx.y * COT;
    const int l0  = blockIdx.x * LT;
    const int tid = threadIdx.x;
    const int tco = (tid / TLn) * 4;
    const int tl  = (tid % TLn) * 4;

    if (fuse) {
        for (int t = tid; t < Cin; t += NT) {
            ssc[t] = g_scale[t];
            ssh[t] = g_shift[t];
        }
    }

    // phase-invariant fill indexing (hoisted out of load_phase)
    int aRow[AE], aOfs[AE];  bool aOk[AE];
    int bRow[BE], bCol[BE];
    #pragma unroll
    for (int j = 0; j < AE; ++j) {
        int t = tid + j * NT;
        int row = t / COT, col = t - row * COT;
        aRow[j] = row;
        aOk[j]  = (co0 + col) < Cout;
        aOfs[j] = row * Cout + co0 + col;
    }
    #pragma unroll
    for (int j = 0; j < BE; ++j) {
        int t = tid + j * NT;
        bRow[j] = t / LT;
        bCol[j] = t - bRow[j] * LT;
    }
    const int HinL = Hin * L;

    __syncthreads();   // ssc/ssh visible before any load_phase

    const int nCh = (Cin + CIC - 1) / CIC;
    const int P   = Nk * 3 * nCh;

    float aReg[AE], bReg[BE];

    auto load_phase = [&](int p) {
        int tap = p / nCh, ch = p - tap * nCh;
        int i = tap / 3, k = tap - i * 3;
        int dd = 1 << (s + i);
        float invd = 1.0f / (float)dd;
        int off = (k - 1) * dd;
        int cc = ch * CIC;
        const float* wbase = wt + (size_t)tap * Cin * Cout + cc * Cout;
        const float* ibase = in + (((size_t)b * Cin + cc) * Hin + (s + i)) * L;
        int lbase = l0 + off;
        #pragma unroll
        for (int j = 0; j < AE; ++j) {
            float v = 0.0f;
            if (aOk[j] && (cc + aRow[j]) < Cin)
                v = wbase[aOfs[j]] * invd;
            aReg[j] = v;
        }
        #pragma unroll
        for (int j = 0; j < BE; ++j) {
            int ci = cc + bRow[j];
            int l  = lbase + bCol[j];
            float v = 0.0f;
            if (ci < Cin && l >= 0 && l < L) {
                v = ibase[bRow[j] * HinL + l];
                if (fuse) v = fmaxf(fmaf(v, ssc[ci], ssh[ci]), 0.0f);
            }
            bReg[j] = v;
        }
    };

    load_phase(0);
    unsigned long long acc2[4][2] = {};

    int ch_cur = 0;
    for (int p = 0; p < P; ++p) {
        const int bufi = p & 1;
        #pragma unroll
        for (int j = 0; j < AE; ++j) {
            int t = tid + j * NT;
            As[bufi][t / COT][t % COT] = aReg[j];
        }
        #pragma unroll
        for (int j = 0; j < BE; ++j) {
            int t = tid + j * NT;
            Bs[bufi][t / LT][t % LT] = bReg[j];
        }
        __syncthreads();
        if (p + 1 < P) load_phase(p + 1);   // LDGs overlap compute below

        int cilim = Cin - ch_cur * CIC;
        if (++ch_cur == nCh) ch_cur = 0;
        if (cilim >= CIC) {
            #pragma unroll
            for (int ci = 0; ci < CIC; ++ci) {
                float4 av = *reinterpret_cast<const float4*>(&As[bufi][ci][tco]);
                ulonglong2 bq = *reinterpret_cast<const ulonglong2*>(&Bs[bufi][ci][tl]);
                float a4[4] = {av.x, av.y, av.z, av.w};
                #pragma unroll
                for (int r = 0; r < 4; ++r) {
                    unsigned long long ap = pack2(a4[r], a4[r]);
                    fma2(acc2[r][0], ap, bq.x);
                    fma2(acc2[r][1], ap, bq.y);
                }
            }
        } else {
            for (int ci = 0; ci < cilim; ++ci) {   // partial chunk: skip zero pad
                float4 av = *reinterpret_cast<const float4*>(&As[bufi][ci][tco]);
                ulonglong2 bq = *reinterpret_cast<const ulonglong2*>(&Bs[bufi][ci][tl]);
                float a4[4] = {av.x, av.y, av.z, av.w};
                #pragma unroll
                for (int r = 0; r < 4; ++r) {
                    unsigned long long ap = pack2(a4[r], a4[r]);
                    fma2(acc2[r][0], ap, bq.x);
                    fma2(acc2[r][1], ap, bq.y);
                }
            }
        }
    }

    #pragma unroll
    for (int r = 0; r < 4; ++r) {
        int co = co0 + tco + r;
        if (co < Cout) {
            size_t ob = (((size_t)b * Cout + co) * Hout + s) * L + l0 + tl;
            float2 lo = unpack2(acc2[r][0]);
            float2 hi = unpack2(acc2[r][1]);
            *reinterpret_cast<float4*>(&out[ob]) = make_float4(lo.x, lo.y, hi.x, hi.y);
        }
    }
}

// ---------------------------------------------------------------------------
// BN stats WITH fused finalize (last-block-done).  grid = (C, S), block = 256
// ---------------------------------------------------------------------------
__global__ void stats_kernel(const float* __restrict__ in,
                             const float* __restrict__ gamma,
                             const float* __restrict__ beta,
                             int C, int HL, double invN, int stage)
{
    const int c  = blockIdx.x;
    const int sp = blockIdx.y, S = gridDim.y;
    float s = 0.0f, s2 = 0.0f;
    for (int b = 0; b < NB; ++b) {
        const float* p = in + ((size_t)b * C + c) * HL;
        for (int r = sp * blockDim.x + threadIdx.x; r < HL; r += S * blockDim.x) {
            float v = p[r];
            s += v; s2 = fmaf(v, v, s2);
        }
    }
    __shared__ float rs[256], rq[256];
    rs[threadIdx.x] = s; rq[threadIdx.x] = s2;
    __syncthreads();
    for (int st = 128; st > 0; st >>= 1) {
        if (threadIdx.x < st) {
            rs[threadIdx.x] += rs[threadIdx.x + st];
            rq[threadIdx.x] += rq[threadIdx.x + st];
        }
        __syncthreads();
    }

    __shared__ bool last;
    if (threadIdx.x == 0) {
        g_psum[c * SMAX + sp] = rs[0];
        g_psqs[c * SMAX + sp] = rq[0];
        __threadfence();
        unsigned int tot = gridDim.x * gridDim.y;
        last = (atomicAdd(&g_tick[stage], 1u) == tot - 1u);
    }
    __syncthreads();

    if (last) {
        __threadfence();
        for (int cc = threadIdx.x; cc < C; cc += blockDim.x) {
            double sd = 0.0, qd = 0.0;
            for (int i = 0; i < S; ++i) {
                sd += (double)g_psum[cc * SMAX + i];
                qd += (double)g_psqs[cc * SMAX + i];
            }
            double m   = sd * invN;
            double var = qd * invN - m * m;
            float inv = rsqrtf((float)var + 2e-5f);
            float sc  = gamma[cc] * inv;
            g_scale[cc] = sc;
            g_shift[cc] = beta[cc] - (float)m * sc;
        }
        __syncthreads();
        if (threadIdx.x == 0) {
            __threadfence();
            g_tick[stage] = 0;
        }
    }
}

// ---------------------------------------------------------------------------
// BN apply + ReLU + pool4 — slab-indexed, float4 loads, no per-element div.
// grid: (ceil(Lout/256), NB*C*H)
// ---------------------------------------------------------------------------
__global__ void bn_pool_kernel(const float* __restrict__ in, float* __restrict__ out,
                               int C, int H, int Lout)
{
    const int y = blockIdx.y;             // y = (b*C + c)*H + h
    const int c = (y / H) % C;
    const float sc = g_scale[c], sh = g_shift[c];
    const float4* p = reinterpret_cast<const float4*>(in + (size_t)y * (Lout * 4));
    float* o = out + (size_t)y * Lout;
    for (int lp = blockIdx.x * blockDim.x + threadIdx.x; lp < Lout;
         lp += gridDim.x * blockDim.x) {
        float4 v = p[lp];
        float y0 = fmaf(v.x, sc, sh);
        float y1 = fmaf(v.y, sc, sh);
        float y2 = fmaf(v.z, sc, sh);
        float y3 = fmaf(v.w, sc, sh);
        o[lp] = fmaxf(fmaxf(fmaxf(y0, y1), fmaxf(y2, y3)), 0.0f);
    }
}

// ---------------------------------------------------------------------------
// Final: fused bn10+relu, mean over L=32, 1x1 classifier -> out [8,10]
// ---------------------------------------------------------------------------
__global__ void final_kernel(const float* __restrict__ in,   // raw [8][408][32]
                             const float* __restrict__ w11,
                             float* __restrict__ out)
{
    __shared__ float mean[NB * 408];
    for (int i = threadIdx.x; i < NB * 408; i += blockDim.x) {
        int c = i % 408;
        float sc = g_scale[c], sh = g_shift[c];
        const float* p = in + (size_t)i * 32;
        float s = 0.0f;
        #pragma unroll
        for (int j = 0; j < 32; ++j)
            s += fmaxf(fmaf(p[j], sc, sh), 0.0f);
        mean[i] = s * (1.0f / 32.0f);
    }
    __syncthreads();
    for (int i = threadIdx.x; i < NB * 10; i += blockDim.x) {
        int b = i / 10, cls = i - b * 10;
        const float* mb = &mean[b * 408];
        const float* wr = &w11[cls * 408];
        float s = 0.0f;
        for (int ci = 0; ci < 408; ++ci) s = fmaf(mb[ci], wr[ci], s);
        out[i] = s;
    }
}

// ---------------------------------------------------------------------------
// Host side
// ---------------------------------------------------------------------------
static int g_stage;   // BN stage counter (stage 0 reserved for lift)

static void bn_stats(const float* in, const float* g, const float* bta, int C, int H, int Lin)
{
    int HL = H * Lin;
    int S = (NB * HL) / (256 * 16);
    if (S < 1) S = 1; if (S > SMAX) S = SMAX;
    double invN = 1.0 / ((double)NB * HL);
    stats_kernel<<<dim3(C, S), 256>>>(in, g, bta, C, HL, invN, g_stage++);
}

static void bn_pool(const float* in, float* out, int C, int H, int Lin)
{
    int Lout = Lin / 4;
    int gx = (Lout + 255) / 256; if (gx > 8) gx = 8;
    bn_pool_kernel<<<dim3(gx, NB * C * H), 256>>>(in, out, C, H, Lout);
}

static void gg(const float* in, const float* wt, float* out,
               int Cin, int Cout, int Hin, int Nk, int L, int fuse)
{
    int Hout = Hin - Nk + 1;
    if (L >= 64)
        gg_kernel<64, 64><<<dim3(L / 64, (Cout + 63) / 64, NB * Hout), 256>>>(
            in, wt, out, Cin, Cout, Hin, Nk, L, fuse);
    else
        gg_kernel<64, 32><<<dim3(L / 32, (Cout + 63) / 64, NB * Hout), 128>>>(
            in, wt, out, Cin, Cout, Hin, Nk, L, fuse);
}

extern "C" void kernel_launch(void* const* d_in, const int* in_sizes, int n_in,
                              void* d_out, int out_size)
{
    const float* x   = (const float*)d_in[0];
    const float* w1  = (const float*)d_in[1];
    const float* wsrc[9];
    for (int i = 0; i < 9; ++i) wsrc[i] = (const float*)d_in[2 + i];   // w2..w10
    const float* w11 = (const float*)d_in[11];
    const float* gb[20];
    for (int i = 0; i < 20; ++i) gb[i] = (const float*)d_in[12 + i];

    float *A, *B, *WT;
    cudaGetSymbolAddress((void**)&A, g_bufA);
    cudaGetSymbolAddress((void**)&B, g_bufB);
    cudaGetSymbolAddress((void**)&WT, g_wT);

    cudaFuncSetAttribute(lift_pool_kernel,
                         cudaFuncAttributeMaxDynamicSharedMemorySize, 98304);

    g_stage = 1;   // stage 0 is lift's fused BN1

    // layer dims: {Cin, Cout, Nk} — must match c_CIN/c_COUT/c_NKK order
    const int ldims[9][3] = {
        {51, 51, 3}, {51, 51, 1}, {51, 102, 3}, {102, 102, 1},
        {102, 204, 3}, {204, 204, 1}, {204, 204, 1}, {204, 408, 3}, {408, 408, 1}
    };
    size_t wofs[10];
    wofs[0] = 0;
    for (int i = 0; i < 9; ++i)
        wofs[i + 1] = wofs[i] + (size_t)ldims[i][0] * ldims[i][1] * ldims[i][2] * 3;

    // single transpose pass for all gg weights
    wtrans_all_kernel<<<1024, 256>>>(wsrc[0], wsrc[1], wsrc[2], wsrc[3], wsrc[4],
                                     wsrc[5], wsrc[6], wsrc[7], wsrc[8], WT);

    // lift + pool4 + BN1 stats + second pool4 (all 9 scales) -> B = A2 [8,51,9,2048]
    {
        size_t smem = (size_t)(79 * 52 + 128 + 78 * 256 + 8) * sizeof(float);
        lift_pool_kernel<<<dim3(LIN / 128, NB, NSC), 416, smem>>>(x, w1, B, gb[0], gb[1]);
    }

    gg(B, WT + wofs[0], A, 51, 51, 9, 3, 2048, 1);    // BN1+ReLU fused at load -> A
    bn_stats(A, gb[2], gb[3], 51, 7, 2048);
    gg(A, WT + wofs[1], B, 51, 51, 7, 1, 2048, 1);    // -> B [8,51,7,2048]
    bn_stats(B, gb[4], gb[5], 51, 7, 2048);
    bn_pool(B, A, 51, 7, 2048);                       // -> A [8,51,7,512]
    gg(A, WT + wofs[2], B, 51, 102, 7, 3, 512, 0);    // -> B [8,102,5,512]
    bn_stats(B, gb[6], gb[7], 102, 5, 512);
    gg(B, WT + wofs[3], A, 102, 102, 5, 1, 512, 1);   // -> A [8,102,5,512]
    bn_stats(A, gb[8], gb[9], 102, 5, 512);
    bn_pool(A, B, 102, 5, 512);                       // -> B [8,102,5,128]
    gg(B, WT + wofs[4], A, 102, 204, 5, 3, 128, 0);   // -> A [8,204,3,128]
    bn_stats(A, gb[10], gb[11], 204, 3, 128);
    gg(A, WT + wofs[5], B, 204, 204, 3, 1, 128, 1);   // -> B [8,204,3,128]
    bn_stats(B, gb[12], gb[13], 204, 3, 128);
    gg(B, WT + wofs[6], A, 204, 204, 3, 1, 128, 1);   // -> A [8,204,3,128]
    bn_stats(A, gb[14], gb[15], 204, 3, 128);
    bn_pool(A, B, 204, 3, 128);                       // -> B [8,204,3,32]
    gg(B, WT + wofs[7], A, 204, 408, 3, 3, 32, 0);    // -> A [8,408,1,32]
    bn_stats(A, gb[16], gb[17], 408, 1, 32);
    gg(A, WT + wofs[8], B, 408, 408, 1, 1, 32, 1);    // -> B [8,408,1,32]
    bn_stats(B, gb[18], gb[19], 408, 1, 32);

    final_kernel<<<1, 512>>>(B, w11, (float*)d_out);
}

// round 17
// speedup vs baseline: 1.0487x; 1.0487x over previous
#include <cuda_runtime.h>

#define NB   8
#define LIN  32768
#define NC1  51
#define NK1  79
#define NSC  9
#define LP1  8192
#define LP2  2048
#define SMAX 64
#define NSLOT 32

// scratch (allocation-free rule: device globals)
__device__ float  g_bufA[30081024];   // ping buffer
__device__ float  g_bufB[7520256];    // pong buffer (= 8*51*9*2048)
__device__ float  g_wT[1800000];      // transposed gg weights [layer][tap][ci][co]
__device__ float  g_psum[408 * SMAX];
__device__ float  g_psqs[408 * SMAX];
__device__ double g_dsum[408 * NSLOT];   // zero-init; re-zeroed by finalize
__device__ double g_dsqs[408 * NSLOT];
__device__ float  g_scale[408];
__device__ float  g_shift[408];
__device__ unsigned int g_tick[16];   // per-BN-stage arrival tickets (self-resetting)

// layer dims for the 9 gg layers: {Cin, Cout, Nk*3}
#define GG_NLAYERS 9
__device__ __constant__ int c_CIN[GG_NLAYERS]  = {51, 51, 51, 102, 102, 204, 204, 204, 408};
__device__ __constant__ int c_COUT[GG_NLAYERS] = {51, 51, 102, 102, 204, 204, 204, 408, 408};
__device__ __constant__ int c_NKK[GG_NLAYERS]  = {9, 3, 9, 3, 9, 3, 3, 9, 3};

// ---------------------------------------------------------------------------
// packed fp32x2 helpers (FFMA2 — only reachable via PTX)
// ---------------------------------------------------------------------------
__device__ __forceinline__ unsigned long long pack2(float lo, float hi) {
    unsigned long long r;
    asm("mov.b64 %0, {%1, %2};" : "=l"(r) : "f"(lo), "f"(hi));
    return r;
}
__device__ __forceinline__ void fma2(unsigned long long& d,
                                     unsigned long long a, unsigned long long b) {
    asm("fma.rn.f32x2 %0, %1, %2, %0;" : "+l"(d) : "l"(a), "l"(b));
}
__device__ __forceinline__ float2 unpack2(unsigned long long v) {
    float2 f;
    asm("mov.b64 {%0, %1}, %2;" : "=f"(f.x), "=f"(f.y) : "l"(v));
    return f;
}

// ---------------------------------------------------------------------------
// finalize tail (last-block-done over double slots): reduces slot partials
// into scale/shift, zeroes slots, resets the ticket. Call from ALL threads.
// ---------------------------------------------------------------------------
__device__ __forceinline__ void bn_finalize_tail(
    const float* __restrict__ gamma, const float* __restrict__ beta,
    int C, double invN, int stage, int tid, int nthreads, unsigned int total)
{
    __shared__ bool last;
    __syncthreads();                      // this block's atomics done
    if (tid == 0) {
        __threadfence();
        last = (atomicAdd(&g_tick[stage], 1u) == total - 1u);
    }
    __syncthreads();
    if (!last) return;
    __threadfence();                      // acquire all partials
    for (int cc = tid; cc < C; cc += nthreads) {
        double sd = 0.0, qd = 0.0;
        #pragma unroll 4
        for (int i = 0; i < NSLOT; ++i) {
            sd += g_dsum[cc * NSLOT + i];
            qd += g_dsqs[cc * NSLOT + i];
            g_dsum[cc * NSLOT + i] = 0.0;
            g_dsqs[cc * NSLOT + i] = 0.0;
        }
        double m   = sd * invN;
        double var = qd * invN - m * m;
        float inv = rsqrtf((float)var + 2e-5f);
        float sc  = gamma[cc] * inv;
        g_scale[cc] = sc;
        g_shift[cc] = beta[cc] - (float)m * sc;
    }
    __syncthreads();
    if (tid == 0) {
        __threadfence();
        g_tick[stage] = 0;                // reset for next graph replay
    }
}

// ---------------------------------------------------------------------------
// One-shot weight transpose for ALL gg layers:
// w[Cout][Cin][NkK] -> wt[tap][ci][co] per layer, concatenated.
// ---------------------------------------------------------------------------
__global__ void wtrans_all_kernel(const float* __restrict__ w0, const float* __restrict__ w1,
                                  const float* __restrict__ w2, const float* __restrict__ w3,
                                  const float* __restrict__ w4, const float* __restrict__ w5,
                                  const float* __restrict__ w6, const float* __restrict__ w7,
                                  const float* __restrict__ w8, float* __restrict__ wt)
{
    const float* ws[GG_NLAYERS] = {w0, w1, w2, w3, w4, w5, w6, w7, w8};
    int total = 0;
    int off[GG_NLAYERS];
    #pragma unroll
    for (int l = 0; l < GG_NLAYERS; ++l) {
        off[l] = total;
        total += c_CIN[l] * c_COUT[l] * c_NKK[l];
    }
    for (int idx = blockIdx.x * blockDim.x + threadIdx.x; idx < total;
         idx += gridDim.x * blockDim.x) {
        int layer = 0;
        #pragma unroll
        for (int l = 1; l < GG_NLAYERS; ++l)
            if (idx >= off[l]) layer = l;
        int local = idx - off[layer];
        int Cout = c_COUT[layer], Cin = c_CIN[layer], NkK = c_NKK[layer];
        int co  = local % Cout;
        int t   = local / Cout;
        int ci  = t % Cin;
        int tap = t / Cin;
        wt[idx] = ws[layer][(co * Cin + ci) * NkK + tap];
    }
}

// ---------------------------------------------------------------------------
// Lift (K=79, dilation 2^s, /2^s) fused with pool4, BN1 STATS, and the
// second pool4 (monotonicity: gamma>0 so relu(bn(max4(A))) needs only max4(A)).
// Writes the TWICE-pooled A2 [8,51,9,2048]; never materializes full A.
// ---------------------------------------------------------------------------
__launch_bounds__(416)
__global__ void lift_pool_kernel(const float* __restrict__ x,
                                 const float* __restrict__ w,
                                 float* __restrict__ out,   // A2 [8][51][9][2048]
                                 const float* __restrict__ gamma,
                                 const float* __restrict__ beta)
{
    extern __shared__ float sm[];
    float* sw = sm;             // [79][52] pre-scaled weights
    float* sx = sm + 79 * 52;   // input window
    const int s = blockIdx.z;
    const int d = 1 << s;
    const float invd = 1.0f / (float)d;
    const int b   = blockIdx.y;
    const int l0  = blockIdx.x * 128;
    const int tid = threadIdx.x;

    for (int t = tid; t < 79 * 52; t += 416) {
        int k = t / 52, co = t - k * 52;
        sw[t] = (co < NC1) ? w[co * NK1 + k] * invd : 0.0f;
    }
    const int nx = 128 + 78 * d + 8;
    const int gb = l0 - 39 * d;
    const float* xb = x + (size_t)b * LIN;
    for (int t = tid; t < nx; t += 416) {
        int g = gb + t;
        sx[t] = (g >= 0 && g < LIN) ? xb[g] : 0.0f;
    }
    __syncthreads();

    const int lg   = tid & 31;
    const int cg   = tid >> 5;
    const int co0  = cg * 4;
    const int base = lg * 4;
    unsigned long long acc2[4][2] = {};

    if (d >= 4) {
        #pragma unroll 4
        for (int k = 0; k < NK1; ++k) {
            ulonglong2 xq = *reinterpret_cast<const ulonglong2*>(&sx[base + k * d]);
            float4 wv = *reinterpret_cast<const float4*>(&sw[k * 52 + co0]);
            float wa[4] = {wv.x, wv.y, wv.z, wv.w};
            #pragma unroll
            for (int r = 0; r < 4; ++r) {
                unsigned long long wp = pack2(wa[r], wa[r]);
                fma2(acc2[r][0], wp, xq.x);
                fma2(acc2[r][1], wp, xq.y);
            }
        }
    } else if (d == 2) {
        float x0 = sx[base], x1 = sx[base+1], x2 = sx[base+2], x3 = sx[base+3];
        for (int k = 0; k < NK1; ++k) {
            float4 wv = *reinterpret_cast<const float4*>(&sw[k * 52 + co0]);
            float wa[4] = {wv.x, wv.y, wv.z, wv.w};
            unsigned long long xp0 = pack2(x0, x1), xp1 = pack2(x2, x3);
            #pragma unroll
            for (int r = 0; r < 4; ++r) {
                unsigned long long wp = pack2(wa[r], wa[r]);
                fma2(acc2[r][0], wp, xp0);
                fma2(acc2[r][1], wp, xp1);
            }
            x0 = x2; x1 = x3;
            x2 = sx[base + 2*k + 4];
            x3 = sx[base + 2*k + 5];
        }
    } else {
        float x0 = sx[base], x1 = sx[base+1], x2 = sx[base+2], x3 = sx[base+3];
        for (int k = 0; k < NK1; ++k) {
            float4 wv = *reinterpret_cast<const float4*>(&sw[k * 52 + co0]);
            float wa[4] = {wv.x, wv.y, wv.z, wv.w};
            unsigned long long xp0 = pack2(x0, x1), xp1 = pack2(x2, x3);
            #pragma unroll
            for (int r = 0; r < 4; ++r) {
                unsigned long long wp = pack2(wa[r], wa[r]);
                fma2(acc2[r][0], wp, xp0);
                fma2(acc2[r][1], wp, xp1);
            }
            x0 = x1; x1 = x2; x2 = x3;
            x3 = sx[base + k + 4];
        }
    }

    // epilogue: A value per (co, pooled pos) -> stats + second pool4 across lanes
    const int lp2  = blockIdx.x * 8 + (lg >> 2);
    const int slot = (blockIdx.x + blockIdx.y * 3 + blockIdx.z * 5) & (NSLOT - 1);
    #pragma unroll
    for (int r = 0; r < 4; ++r) {
        float2 a = unpack2(acc2[r][0]);
        float2 c = unpack2(acc2[r][1]);
        float m = fmaxf(fmaxf(a.x, a.y), fmaxf(c.x, c.y));   // A[b,co,s,lp]

        // BN1 stats over A (full 32-lane reduce)
        float sv = m, qv = m * m;
        #pragma unroll
        for (int del = 16; del > 0; del >>= 1) {
            sv += __shfl_down_sync(0xffffffffu, sv, del);
            qv += __shfl_down_sync(0xffffffffu, qv, del);
        }
        // second pool4 across lane quads
        float p = m;
        p = fmaxf(p, __shfl_xor_sync(0xffffffffu, p, 1));
        p = fmaxf(p, __shfl_xor_sync(0xffffffffu, p, 2));

        int co = co0 + r;
        if (co < NC1) {
            if ((lg & 3) == 0)
                out[(((size_t)b * NC1 + co) * NSC + s) * LP2 + lp2] = p;
            if (lg == 0) {
                atomicAdd(&g_dsum[co * NSLOT + slot], (double)sv);
                atomicAdd(&g_dsqs[co * NSLOT + slot], (double)qv);
            }
        }
    }

    bn_finalize_tail(gamma, beta, NC1, 1.0 / ((double)NB * NSC * LP1), 0,
                     tid, 416, gridDim.x * gridDim.y * gridDim.z);
}

// ---------------------------------------------------------------------------
// GConvGG: tiled GEMM over ci per (i,k) tap. CIC=17 — every layer width
// (51/102/204/408) is a multiple of 17, so chunking is EXACT: no zero pad,
// no partial-chunk branch, no ci guards, 25% fewer phases on 51-ch layers.
// Ping-pong double-buffered fills with hoisted indexing. 4x4 tile on fp32x2.
// fuse != 0: per-channel BN + ReLU applied at input-tile load.
// ---------------------------------------------------------------------------
template <int COT, int LT>
__launch_bounds__((COT/4)*(LT/4))
__global__ void gg_kernel(const float* __restrict__ in, const float* __restrict__ wt,
                          float* __restrict__ out,
                          int Cin, int Cout, int Hin, int Nk, int L, int fuse)
{
    const int CIC = 17;
    const int TLn = LT / 4;
    const int NT  = (COT/4) * TLn;
    const int AE  = (CIC * COT + NT - 1) / NT;
    const int BE  = (CIC * LT + NT - 1) / NT;
    __shared__ __align__(16) float As[2][CIC][COT];
    __shared__ __align__(16) float Bs[2][CIC][LT];
    __shared__ float ssc[408], ssh[408];

    const int Hout = Hin - Nk + 1;
    const int s   = blockIdx.z % Hout;
    const int b   = blockIdx.z / Hout;
    const int co0 = blockIdx.y * COT;
    const int l0  = blockIdx.x * LT;
    const int tid = threadIdx.x;
    const int tco = (tid / TLn) * 4;
    const int tl  = (tid % TLn) * 4;

    if (fuse) {
        for (int t = tid; t < Cin; t += NT) {
            ssc[t] = g_scale[t];
            ssh[t] = g_shift[t];
        }
    }

    // phase-invariant fill indexing (hoisted; validity flags for ragged tail)
    int aRow[AE], aCol[AE], aOfs[AE];  bool aIn[AE], aOk[AE];
    int bRow[BE], bCol[BE];            bool bIn[BE];
    #pragma unroll
    for (int j = 0; j < AE; ++j) {
        int t = tid + j * NT;
        aIn[j] = t < CIC * COT;
        int row = t / COT, col = t - row * COT;
        aRow[j] = row; aCol[j] = col;
        aOk[j]  = aIn[j] && (co0 + col) < Cout;
        aOfs[j] = row * Cout + co0 + col;
    }
    #pragma unroll
    for (int j = 0; j < BE; ++j) {
        int t = tid + j * NT;
        bIn[j] = t < CIC * LT;
        bRow[j] = t / LT;
        bCol[j] = t - bRow[j] * LT;
    }
    const int HinL = Hin * L;

    __syncthreads();   // ssc/ssh visible before any load_phase

    const int nCh = Cin / CIC;          // exact for all layers
    const int P   = Nk * 3 * nCh;

    float aReg[AE], bReg[BE];

    auto load_phase = [&](int p) {
        int tap = p / nCh, ch = p - tap * nCh;
        int i = tap / 3, k = tap - i * 3;
        int dd = 1 << (s + i);
        float invd = 1.0f / (float)dd;
        int off = (k - 1) * dd;
        int cc = ch * CIC;
        const float* wbase = wt + (size_t)tap * Cin * Cout + cc * Cout;
        const float* ibase = in + (((size_t)b * Cin + cc) * Hin + (s + i)) * L;
        int lbase = l0 + off;
        #pragma unroll
        for (int j = 0; j < AE; ++j)
            aReg[j] = aOk[j] ? wbase[aOfs[j]] * invd : 0.0f;
        #pragma unroll
        for (int j = 0; j < BE; ++j) {
            float v = 0.0f;
            if (bIn[j]) {
                int ci = cc + bRow[j];
                int l  = lbase + bCol[j];
                if (l >= 0 && l < L) {
                    v = ibase[bRow[j] * HinL + l];
                    if (fuse) v = fmaxf(fmaf(v, ssc[ci], ssh[ci]), 0.0f);
                }
            }
            bReg[j] = v;
        }
    };

    load_phase(0);
    unsigned long long acc2[4][2] = {};

    for (int p = 0; p < P; ++p) {
        const int bufi = p & 1;
        #pragma unroll
        for (int j = 0; j < AE; ++j)
            if (aIn[j]) As[bufi][aRow[j]][aCol[j]] = aReg[j];
        #pragma unroll
        for (int j = 0; j < BE; ++j)
            if (bIn[j]) Bs[bufi][bRow[j]][bCol[j]] = bReg[j];
        __syncthreads();
        if (p + 1 < P) load_phase(p + 1);   // LDGs overlap compute below
        #pragma unroll
        for (int ci = 0; ci < CIC; ++ci) {
            float4 av = *reinterpret_cast<const float4*>(&As[bufi][ci][tco]);
            ulonglong2 bq = *reinterpret_cast<const ulonglong2*>(&Bs[bufi][ci][tl]);
            float a4[4] = {av.x, av.y, av.z, av.w};
            #pragma unroll
            for (int r = 0; r < 4; ++r) {
                unsigned long long ap = pack2(a4[r], a4[r]);
                fma2(acc2[r][0], ap, bq.x);
                fma2(acc2[r][1], ap, bq.y);
            }
        }
    }

    #pragma unroll
    for (int r = 0; r < 4; ++r) {
        int co = co0 + tco + r;
        if (co < Cout) {
            size_t ob = (((size_t)b * Cout + co) * Hout + s) * L + l0 + tl;
            float2 lo = unpack2(acc2[r][0]);
            float2 hi = unpack2(acc2[r][1]);
            *reinterpret_cast<float4*>(&out[ob]) = make_float4(lo.x, lo.y, hi.x, hi.y);
        }
    }
}

// ---------------------------------------------------------------------------
// BN stats WITH fused finalize (last-block-done). float4 loads (HL % 4 == 0).
// grid = (C, S), block = 256
// ---------------------------------------------------------------------------
__global__ void stats_kernel(const float* __restrict__ in,
                             const float* __restrict__ gamma,
                             const float* __restrict__ beta,
                             int C, int HL, double invN, int stage)
{
    const int c  = blockIdx.x;
    const int sp = blockIdx.y, S = gridDim.y;
    const int HL4 = HL >> 2;
    float s = 0.0f, s2 = 0.0f;
    for (int b = 0; b < NB; ++b) {
        const float4* p = reinterpret_cast<const float4*>(in + ((size_t)b * C + c) * HL);
        for (int r = sp * blockDim.x + threadIdx.x; r < HL4; r += S * blockDim.x) {
            float4 v = p[r];
            s += v.x + v.y + v.z + v.w;
            s2 = fmaf(v.x, v.x, s2);
            s2 = fmaf(v.y, v.y, s2);
            s2 = fmaf(v.z, v.z, s2);
            s2 = fmaf(v.w, v.w, s2);
        }
    }
    __shared__ float rs[256], rq[256];
    rs[threadIdx.x] = s; rq[threadIdx.x] = s2;
    __syncthreads();
    for (int st = 128; st > 0; st >>= 1) {
        if (threadIdx.x < st) {
            rs[threadIdx.x] += rs[threadIdx.x + st];
            rq[threadIdx.x] += rq[threadIdx.x + st];
        }
        __syncthreads();
    }

    __shared__ bool last;
    if (threadIdx.x == 0) {
        g_psum[c * SMAX + sp] = rs[0];
        g_psqs[c * SMAX + sp] = rq[0];
        __threadfence();
        unsigned int tot = gridDim.x * gridDim.y;
        last = (atomicAdd(&g_tick[stage], 1u) == tot - 1u);
    }
    __syncthreads();

    if (last) {
        __threadfence();
        for (int cc = threadIdx.x; cc < C; cc += blockDim.x) {
            double sd = 0.0, qd = 0.0;
            for (int i = 0; i < S; ++i) {
                sd += (double)g_psum[cc * SMAX + i];
                qd += (double)g_psqs[cc * SMAX + i];
            }
            double m   = sd * invN;
            double var = qd * invN - m * m;
            float inv = rsqrtf((float)var + 2e-5f);
            float sc  = gamma[cc] * inv;
            g_scale[cc] = sc;
            g_shift[cc] = beta[cc] - (float)m * sc;
        }
        __syncthreads();
        if (threadIdx.x == 0) {
            __threadfence();
            g_tick[stage] = 0;
        }
    }
}

// ---------------------------------------------------------------------------
// BN apply + ReLU + pool4 — slab-indexed, float4 loads, no per-element div.
// grid: (ceil(Lout/256), NB*C*H)
// ---------------------------------------------------------------------------
__global__ void bn_pool_kernel(const float* __restrict__ in, float* __restrict__ out,
                               int C, int H, int Lout)
{
    const int y = blockIdx.y;             // y = (b*C + c)*H + h
    const int c = (y / H) % C;
    const float sc = g_scale[c], sh = g_shift[c];
    const float4* p = reinterpret_cast<const float4*>(in + (size_t)y * (Lout * 4));
    float* o = out + (size_t)y * Lout;
    for (int lp = blockIdx.x * blockDim.x + threadIdx.x; lp < Lout;
         lp += gridDim.x * blockDim.x) {
        float4 v = p[lp];
        float y0 = fmaf(v.x, sc, sh);
        float y1 = fmaf(v.y, sc, sh);
        float y2 = fmaf(v.z, sc, sh);
        float y3 = fmaf(v.w, sc, sh);
        o[lp] = fmaxf(fmaxf(fmaxf(y0, y1), fmaxf(y2, y3)), 0.0f);
    }
}

// ---------------------------------------------------------------------------
// Final: fused bn10+relu, mean over L=32, 1x1 classifier -> out [8,10]
// ---------------------------------------------------------------------------
__global__ void final_kernel(const float* __restrict__ in,   // raw [8][408][32]
                             const float* __restrict__ w11,
                             float* __restrict__ out)
{
    __shared__ float mean[NB * 408];
    for (int i = threadIdx.x; i < NB * 408; i += blockDim.x) {
        int c = i % 408;
        float sc = g_scale[c], sh = g_shift[c];
        const float* p = in + (size_t)i * 32;
        float s = 0.0f;
        #pragma unroll
        for (int j = 0; j < 32; ++j)
            s += fmaxf(fmaf(p[j], sc, sh), 0.0f);
        mean[i] = s * (1.0f / 32.0f);
    }
    __syncthreads();
    for (int i = threadIdx.x; i < NB * 10; i += blockDim.x) {
        int b = i / 10, cls = i - b * 10;
        const float* mb = &mean[b * 408];
        const float* wr = &w11[cls * 408];
        float s = 0.0f;
        for (int ci = 0; ci < 408; ++ci) s = fmaf(mb[ci], wr[ci], s);
        out[i] = s;
    }
}

// ---------------------------------------------------------------------------
// Host side
// ---------------------------------------------------------------------------
static int g_stage;   // BN stage counter (stage 0 reserved for lift)

static void bn_stats(const float* in, const float* g, const float* bta, int C, int H, int Lin)
{
    int HL = H * Lin;
    int S = (NB * HL) / (256 * 16);
    if (S < 1) S = 1; if (S > SMAX) S = SMAX;
    double invN = 1.0 / ((double)NB * HL);
    stats_kernel<<<dim3(C, S), 256>>>(in, g, bta, C, HL, invN, g_stage++);
}

static void bn_pool(const float* in, float* out, int C, int H, int Lin)
{
    int Lout = Lin / 4;
    int gx = (Lout + 255) / 256; if (gx > 8) gx = 8;
    bn_pool_kernel<<<dim3(gx, NB * C * H), 256>>>(in, out, C, H, Lout);
}

static void gg(const float* in, const float* wt, float* out,
               int Cin, int Cout, int Hin, int Nk, int L, int fuse)
{
    int Hout = Hin - Nk + 1;
    if (L >= 64)
        gg_kernel<64, 64><<<dim3(L / 64, (Cout + 63) / 64, NB * Hout), 256>>>(
            in, wt, out, Cin, Cout, Hin, Nk, L, fuse);
    else
        gg_kernel<64, 32><<<dim3(L / 32, (Cout + 63) / 64, NB * Hout), 128>>>(
            in, wt, out, Cin, Cout, Hin, Nk, L, fuse);
}

extern "C" void kernel_launch(void* const* d_in, const int* in_sizes, int n_in,
                              void* d_out, int out_size)
{
    const float* x   = (const float*)d_in[0];
    const float* w1  = (const float*)d_in[1];
    const float* wsrc[9];
    for (int i = 0; i < 9; ++i) wsrc[i] = (const float*)d_in[2 + i];   // w2..w10
    const float* w11 = (const float*)d_in[11];
    const float* gb[20];
    for (int i = 0; i < 20; ++i) gb[i] = (const float*)d_in[12 + i];

    float *A, *B, *WT;
    cudaGetSymbolAddress((void**)&A, g_bufA);
    cudaGetSymbolAddress((void**)&B, g_bufB);
    cudaGetSymbolAddress((void**)&WT, g_wT);

    cudaFuncSetAttribute(lift_pool_kernel,
                         cudaFuncAttributeMaxDynamicSharedMemorySize, 98304);

    g_stage = 1;   // stage 0 is lift's fused BN1

    // layer dims: {Cin, Cout, Nk} — must match c_CIN/c_COUT/c_NKK order
    const int ldims[9][3] = {
        {51, 51, 3}, {51, 51, 1}, {51, 102, 3}, {102, 102, 1},
        {102, 204, 3}, {204, 204, 1}, {204, 204, 1}, {204, 408, 3}, {408, 408, 1}
    };
    size_t wofs[10];
    wofs[0] = 0;
    for (int i = 0; i < 9; ++i)
        wofs[i + 1] = wofs[i] + (size_t)ldims[i][0] * ldims[i][1] * ldims[i][2] * 3;

    // single transpose pass for all gg weights
    wtrans_all_kernel<<<1024, 256>>>(wsrc[0], wsrc[1], wsrc[2], wsrc[3], wsrc[4],
                                     wsrc[5], wsrc[6], wsrc[7], wsrc[8], WT);

    // lift + pool4 + BN1 stats + second pool4 (all 9 scales) -> B = A2 [8,51,9,2048]
    {
        size_t smem = (size_t)(79 * 52 + 128 + 78 * 256 + 8) * sizeof(float);
        lift_pool_kernel<<<dim3(LIN / 128, NB, NSC), 416, smem>>>(x, w1, B, gb[0], gb[1]);
    }

    gg(B, WT + wofs[0], A, 51, 51, 9, 3, 2048, 1);    // BN1+ReLU fused at load -> A
    bn_stats(A, gb[2], gb[3], 51, 7, 2048);
    gg(A, WT + wofs[1], B, 51, 51, 7, 1, 2048, 1);    // -> B [8,51,7,2048]
    bn_stats(B, gb[4], gb[5], 51, 7, 2048);
    bn_pool(B, A, 51, 7, 2048);                       // -> A [8,51,7,512]
    gg(A, WT + wofs[2], B, 51, 102, 7, 3, 512, 0);    // -> B [8,102,5,512]
    bn_stats(B, gb[6], gb[7], 102, 5, 512);
    gg(B, WT + wofs[3], A, 102, 102, 5, 1, 512, 1);   // -> A [8,102,5,512]
    bn_stats(A, gb[8], gb[9], 102, 5, 512);
    bn_pool(A, B, 102, 5, 512);                       // -> B [8,102,5,128]
    gg(B, WT + wofs[4], A, 102, 204, 5, 3, 128, 0);   // -> A [8,204,3,128]
    bn_stats(A, gb[10], gb[11], 204, 3, 128);
    gg(A, WT + wofs[5], B, 204, 204, 3, 1, 128, 1);   // -> B [8,204,3,128]
    bn_stats(B, gb[12], gb[13], 204, 3, 128);
    gg(B, WT + wofs[6], A, 204, 204, 3, 1, 128, 1);   // -> A [8,204,3,128]
    bn_stats(A, gb[14], gb[15], 204, 3, 128);
    bn_pool(A, B, 204, 3, 128);                       // -> B [8,204,3,32]
    gg(B, WT + wofs[7], A, 204, 408, 3, 3, 32, 0);    // -> A [8,408,1,32]
    bn_stats(A, gb[16], gb[17], 408, 1, 32);
    gg(A, WT + wofs[8], B, 408, 408, 1, 1, 32, 1);    // -> B [8,408,1,32]
    bn_stats(B, gb[18], gb[19], 408, 1, 32);

    final_kernel<<<1, 512>>>(B, w11, (float*)d_out);
}